// round 8
// baseline (speedup 1.0000x reference)
#include <cuda_runtime.h>
#include <cuda_fp16.h>
#include <cstdint>
#include <cstddef>

#define TOK   8192
#define DIM   1024
#define HID   4096
#define NEXP  8

using u32 = uint32_t;

// ---------------------------------------------------------------------------
// device scratch
// ---------------------------------------------------------------------------
__device__ int    g_count[NEXP];
__device__ int    g_base[NEXP];
__device__ int    g_fill[NEXP];
__device__ int    g_topk_idx[TOK * 2];
__device__ float  g_topk_w[TOK * 2];
__device__ int    g_tok[TOK * 2];
__device__ float  g_gate[TOK * 2];
__device__ int    g_slot[TOK * 2];
__device__ __half g_xh[(size_t)TOK * DIM];
__device__ __half g_w1h[(size_t)NEXP * HID * DIM];   // [e][n(HID)][k(DIM)] K-major
__device__ __half g_w2h[(size_t)NEXP * DIM * HID];   // [e][n(DIM)][k(HID)] K-major
__device__ __half g_hid[(size_t)TOK * 2 * HID];
__device__ float  g_partial[(size_t)TOK * 2 * DIM];

// ---------------------------------------------------------------------------
// PTX helpers (baseline PTX ISA: ldmatrix / mma.sync / cp.async)
// ---------------------------------------------------------------------------
__device__ __forceinline__ u32 smem_u32(const void* p) {
    u32 a;
    asm("{ .reg .u64 t; cvta.to.shared.u64 t, %1; cvt.u32.u64 %0, t; }"
        : "=r"(a) : "l"(p));
    return a;
}
__device__ __forceinline__ u32 sw128(u32 off) { return off ^ ((off >> 3) & 0x70); }

__device__ __forceinline__ void cp16(u32 saddr, const void* gptr) {
    asm volatile("cp.async.cg.shared.global [%0], [%1], 16;"
                 :: "r"(saddr), "l"(gptr));
}
#define CP_COMMIT() asm volatile("cp.async.commit_group;" ::: "memory")
#define CP_WAIT1()  asm volatile("cp.async.wait_group 1;" ::: "memory")
#define CP_WAIT0()  asm volatile("cp.async.wait_group 0;" ::: "memory")

__device__ __forceinline__ void ldsm4(u32* r, u32 addr) {
    asm volatile("ldmatrix.sync.aligned.m8n8.x4.shared.b16 {%0,%1,%2,%3}, [%4];"
                 : "=r"(r[0]), "=r"(r[1]), "=r"(r[2]), "=r"(r[3]) : "r"(addr));
}
__device__ __forceinline__ void mma16816(float* d, const u32* a, u32 b0, u32 b1) {
    asm volatile(
        "mma.sync.aligned.m16n8k16.row.col.f32.f16.f16.f32 "
        "{%0,%1,%2,%3}, {%4,%5,%6,%7}, {%8,%9}, {%0,%1,%2,%3};"
        : "+f"(d[0]), "+f"(d[1]), "+f"(d[2]), "+f"(d[3])
        : "r"(a[0]), "r"(a[1]), "r"(a[2]), "r"(a[3]), "r"(b0), "r"(b1));
}

// ---------------------------------------------------------------------------
// gating chain
// ---------------------------------------------------------------------------
__global__ void k_init() { if (threadIdx.x < NEXP) g_count[threadIdx.x] = 0; }

__global__ void k_gate(const float* __restrict__ x,
                       const float* __restrict__ Wg,
                       const float* __restrict__ bg) {
    int warp = (blockIdx.x * blockDim.x + threadIdx.x) >> 5;
    int lane = threadIdx.x & 31;
    if (warp >= TOK) return;
    const float* xp = x + (size_t)warp * DIM;
    float acc[8] = {0,0,0,0,0,0,0,0};
    for (int d = lane; d < DIM; d += 32) {
        float xv = xp[d];
        const float4* w = (const float4*)(Wg + d * 8);
        float4 w0 = w[0], w1 = w[1];
        acc[0] += xv * w0.x; acc[1] += xv * w0.y;
        acc[2] += xv * w0.z; acc[3] += xv * w0.w;
        acc[4] += xv * w1.x; acc[5] += xv * w1.y;
        acc[6] += xv * w1.z; acc[7] += xv * w1.w;
    }
#pragma unroll
    for (int off = 16; off > 0; off >>= 1)
#pragma unroll
        for (int e = 0; e < 8; e++)
            acc[e] += __shfl_xor_sync(0xffffffffu, acc[e], off);
    if (lane == 0) {
        float l[8], m = -1e30f;
#pragma unroll
        for (int e = 0; e < 8; e++) { l[e] = acc[e] + bg[e]; m = fmaxf(m, l[e]); }
        float p[8], s = 0.f;
#pragma unroll
        for (int e = 0; e < 8; e++) { p[e] = expf(l[e] - m); s += p[e]; }
        int i1 = 0;
#pragma unroll
        for (int e = 1; e < 8; e++) if (p[e] > p[i1]) i1 = e;
        int i2 = (i1 == 0) ? 1 : 0;
#pragma unroll
        for (int e = 0; e < 8; e++) if (e != i1 && p[e] > p[i2]) i2 = e;
        float inv = 1.f / s;
        g_topk_idx[warp*2]   = i1; g_topk_w[warp*2]   = p[i1] * inv;
        g_topk_idx[warp*2+1] = i2; g_topk_w[warp*2+1] = p[i2] * inv;
        atomicAdd(&g_count[i1], 1);
        atomicAdd(&g_count[i2], 1);
    }
}

__global__ void k_scan() {
    if (threadIdx.x == 0 && blockIdx.x == 0) {
        int s = 0;
        for (int e = 0; e < NEXP; e++) { g_base[e] = s; s += g_count[e]; g_fill[e] = 0; }
    }
}

__global__ void k_assign() {
    int t = blockIdx.x * blockDim.x + threadIdx.x;
    if (t >= TOK) return;
#pragma unroll
    for (int k = 0; k < 2; k++) {
        int   e = g_topk_idx[t*2 + k];
        float w = g_topk_w[t*2 + k];
        int pos = g_base[e] + atomicAdd(&g_fill[e], 1);
        g_tok[pos]  = t;
        g_gate[pos] = w;
        g_slot[t*2 + k] = pos;
    }
}

// ---------------------------------------------------------------------------
// conversion prepasses: x -> fp16; W -> transposed (K-major) fp16
// ---------------------------------------------------------------------------
__global__ void k_conv_x(const float* __restrict__ x) {
    int i = blockIdx.x * blockDim.x + threadIdx.x;   // one float4 each
    float4 v = ((const float4*)x)[i];
    __half2* ph = (__half2*)g_xh;
    ph[2*i]   = __halves2half2(__float2half(v.x), __float2half(v.y));
    ph[2*i+1] = __halves2half2(__float2half(v.z), __float2half(v.w));
}

__device__ __forceinline__ void trans_body(const float* __restrict__ W,
                                           __half* __restrict__ Wh,
                                           int KD, int ND) {
    __shared__ float s[32][33];
    int e  = blockIdx.z;
    int n0 = blockIdx.x * 32, k0 = blockIdx.y * 32;
    int tx = threadIdx.x, ty = threadIdx.y;           // 32 x 8
    const float* Wp = W + (size_t)e * KD * ND;
#pragma unroll
    for (int j = 0; j < 4; j++)
        s[ty + 8*j][tx] = Wp[(size_t)(k0 + ty + 8*j) * ND + n0 + tx];
    __syncthreads();
    size_t ob = (size_t)e * ND * KD;
#pragma unroll
    for (int j = 0; j < 4; j++) {
        float v = s[tx][ty + 8*j];
        size_t o = ob + (size_t)(n0 + ty + 8*j) * KD + k0 + tx;
        Wh[o] = __float2half(v);
    }
}
__global__ void k_trans_w1(const float* __restrict__ W) { trans_body(W, g_w1h, DIM, HID); }
__global__ void k_trans_w2(const float* __restrict__ W) { trans_body(W, g_w2h, HID, DIM); }

// ---------------------------------------------------------------------------
// GEMM1 (exact R6 config): CTA 128x128, KC=64, 2-stage, 256 thr, 2 CTAs/SM
// warp layout: 8 warps = 4(m) x 2(n); warp tile 32(m) x 64(n)
// ---------------------------------------------------------------------------
__global__ __launch_bounds__(256, 2) void k_gemm1_mma(const float* __restrict__ bias_all) {
    constexpr int NC  = DIM / 64;
    constexpr int STG = 32768;
    constexpr int AH = 0, BH = 16384;

    const int e    = blockIdx.z;
    const int cnt  = g_count[e];
    const int row0 = blockIdx.y * 128;
    if (row0 >= cnt) return;
    const int base = g_base[e];
    const int n0   = blockIdx.x * 128;

    const __half* __restrict__ Ah = g_xh;
    const __half* __restrict__ Bh = g_w1h + (size_t)e * HID * DIM;
    const float* __restrict__ bias = bias_all + (size_t)e * HID;

    extern __shared__ char smem[];
    const u32 sbase = smem_u32(smem);
    const int tid = threadIdx.x, wid = tid >> 5, lane = tid & 31;
    const int warp_m = wid & 3, warp_n = wid >> 2;

    const int lane8 = tid & 7, r32 = tid >> 3;
    int aoff[4], boff[4];
    u32 sAB[4];
#pragma unroll
    for (int i = 0; i < 4; i++) {
        int ridx = r32 + 32 * i;
        int rc = min(row0 + ridx, cnt - 1);
        aoff[i] = g_tok[base + rc] * DIM;
        boff[i] = (n0 + ridx) * DIM;
        sAB[i]  = sw128((u32)(ridx * 128 + lane8 * 16));
    }

    float acc[2][8][4];
#pragma unroll
    for (int im = 0; im < 2; im++)
#pragma unroll
        for (int j = 0; j < 8; j++)
#pragma unroll
            for (int q = 0; q < 4; q++) acc[im][j][q] = 0.f;

    const int lrow = (lane & 7) + ((lane >> 3) & 1) * 8;
    u32 rowA[2], rowB[4];
#pragma unroll
    for (int im = 0; im < 2; im++)
        rowA[im] = (u32)((warp_m * 32 + im * 16 + lrow) * 128);
#pragma unroll
    for (int p = 0; p < 4; p++)
        rowB[p] = (u32)((warp_n * 64 + p * 16 + lrow) * 128);
    const u32 bcolbase = ((lane >> 4) & 1) * 16;

    auto issue = [&](int ic) {
        const int co = ic * 64 + lane8 * 8;
        const u32 st = sbase + (u32)((ic & 1) * STG);
#pragma unroll
        for (int i = 0; i < 4; i++) {
            cp16(st + AH + sAB[i], Ah + aoff[i] + co);
            cp16(st + BH + sAB[i], Bh + boff[i] + co);
        }
        CP_COMMIT();
    };

    issue(0);
#pragma unroll 1
    for (int ic = 0; ic < NC; ic++) {
        if (ic + 1 < NC) { issue(ic + 1); CP_WAIT1(); }
        else             { CP_WAIT0(); }
        __syncthreads();
        const u32 st = sbase + (u32)((ic & 1) * STG);
#pragma unroll
        for (int s = 0; s < 4; s++) {
            const u32 bcol = (u32)(s * 32) + bcolbase;
            u32 a_h[2][4];
#pragma unroll
            for (int im = 0; im < 2; im++)
                ldsm4(a_h[im], st + AH + sw128(rowA[im] + bcol));
#pragma unroll
            for (int p = 0; p < 4; p++) {
                u32 b_h[4];
                ldsm4(b_h, st + BH + sw128(rowB[p] + bcol));
#pragma unroll
                for (int im = 0; im < 2; im++) {
                    mma16816(acc[im][2*p],   a_h[im], b_h[0], b_h[2]);
                    mma16816(acc[im][2*p+1], a_h[im], b_h[1], b_h[3]);
                }
            }
        }
        __syncthreads();
    }

    const int crow = lane >> 2;
    const int ccol = (lane & 3) * 2;
#pragma unroll
    for (int im = 0; im < 2; im++) {
#pragma unroll
        for (int j = 0; j < 8; j++) {
            const int p = j >> 1, q = j & 1;
            const int col = n0 + warp_n * 64 + p * 16 + q * 8 + ccol;
            const float2 bb = *(const float2*)(bias + col);
            const int r0g = row0 + warp_m * 32 + im * 16 + crow;
            float* a = acc[im][j];
#pragma unroll
            for (int h = 0; h < 2; h++) {
                int rg = r0g + h * 8;
                if (rg < cnt) {
                    float v0 = fmaxf(a[2*h]   + bb.x, 0.f);
                    float v1 = fmaxf(a[2*h+1] + bb.y, 0.f);
                    __half2 ph = __halves2half2(__float2half(v0), __float2half(v1));
                    size_t o = (size_t)(base + rg) * HID + col;
                    *(u32*)(g_hid + o) = *reinterpret_cast<u32*>(&ph);
                }
            }
        }
    }
}

// ---------------------------------------------------------------------------
// GEMM2: CTA 256(m) x 128(n), KC=64, 2-stage, 512 thr, 1 CTA/SM
// warp layout: 16 warps = 8(m) x 2(n); warp tile 32(m) x 64(n) (same microkernel)
// smem stage: [Ah 32K][Bh 16K] = 48KB, 2 stages = 96KB
// Halves W2 traffic vs TM=128 (y-block count per expert halves).
// ---------------------------------------------------------------------------
__global__ __launch_bounds__(512, 1) void k_gemm2_mma(const float* __restrict__ bias_all) {
    constexpr int NC  = HID / 64;
    constexpr int STG = 49152;
    constexpr int AH = 0, BH = 32768;

    const int e    = blockIdx.z;
    const int cnt  = g_count[e];
    const int row0 = blockIdx.y * 256;
    if (row0 >= cnt) return;
    const int base = g_base[e];
    const int n0   = blockIdx.x * 128;

    const __half* __restrict__ Ah = g_hid;
    const __half* __restrict__ Bh = g_w2h + (size_t)e * DIM * HID;
    const float* __restrict__ bias = bias_all + (size_t)e * DIM;

    extern __shared__ char smem[];
    const u32 sbase = smem_u32(smem);
    const int tid = threadIdx.x, wid = tid >> 5, lane = tid & 31;
    const int warp_m = wid & 7, warp_n = wid >> 3;

    // loader: 512 threads; lane8 = 16B chunk, r64 = row 0..63
    const int lane8 = tid & 7, r64 = tid >> 3;
    int aoff[4], boff[2];
    u32 sA[4], sB[2];
#pragma unroll
    for (int i = 0; i < 4; i++) {
        int ridx = r64 + 64 * i;
        int rc = min(row0 + ridx, cnt - 1);
        aoff[i] = (base + rc) * HID;
        sA[i]   = sw128((u32)(ridx * 128 + lane8 * 16));
    }
#pragma unroll
    for (int i = 0; i < 2; i++) {
        int ridx = r64 + 64 * i;
        boff[i] = (n0 + ridx) * HID;
        sB[i]   = sw128((u32)(ridx * 128 + lane8 * 16));
    }

    float acc[2][8][4];
#pragma unroll
    for (int im = 0; im < 2; im++)
#pragma unroll
        for (int j = 0; j < 8; j++)
#pragma unroll
            for (int q = 0; q < 4; q++) acc[im][j][q] = 0.f;

    const int lrow = (lane & 7) + ((lane >> 3) & 1) * 8;
    u32 rowA[2], rowB[4];
#pragma unroll
    for (int im = 0; im < 2; im++)
        rowA[im] = (u32)((warp_m * 32 + im * 16 + lrow) * 128);
#pragma unroll
    for (int p = 0; p < 4; p++)
        rowB[p] = (u32)((warp_n * 64 + p * 16 + lrow) * 128);
    const u32 bcolbase = ((lane >> 4) & 1) * 16;

    auto issue = [&](int ic) {
        const int co = ic * 64 + lane8 * 8;
        const u32 st = sbase + (u32)((ic & 1) * STG);
#pragma unroll
        for (int i = 0; i < 4; i++)
            cp16(st + AH + sA[i], Ah + aoff[i] + co);
#pragma unroll
        for (int i = 0; i < 2; i++)
            cp16(st + BH + sB[i], Bh + boff[i] + co);
        CP_COMMIT();
    };

    issue(0);
#pragma unroll 1
    for (int ic = 0; ic < NC; ic++) {
        if (ic + 1 < NC) { issue(ic + 1); CP_WAIT1(); }
        else             { CP_WAIT0(); }
        __syncthreads();
        const u32 st = sbase + (u32)((ic & 1) * STG);
#pragma unroll
        for (int s = 0; s < 4; s++) {
            const u32 bcol = (u32)(s * 32) + bcolbase;
            u32 a_h[2][4];
#pragma unroll
            for (int im = 0; im < 2; im++)
                ldsm4(a_h[im], st + AH + sw128(rowA[im] + bcol));
#pragma unroll
            for (int p = 0; p < 4; p++) {
                u32 b_h[4];
                ldsm4(b_h, st + BH + sw128(rowB[p] + bcol));
#pragma unroll
                for (int im = 0; im < 2; im++) {
                    mma16816(acc[im][2*p],   a_h[im], b_h[0], b_h[2]);
                    mma16816(acc[im][2*p+1], a_h[im], b_h[1], b_h[3]);
                }
            }
        }
        __syncthreads();
    }

    const int crow = lane >> 2;
    const int ccol = (lane & 3) * 2;
#pragma unroll
    for (int im = 0; im < 2; im++) {
#pragma unroll
        for (int j = 0; j < 8; j++) {
            const int p = j >> 1, q = j & 1;
            const int col = n0 + warp_n * 64 + p * 16 + q * 8 + ccol;
            const float2 bb = *(const float2*)(bias + col);
            const int r0g = row0 + warp_m * 32 + im * 16 + crow;
            float* a = acc[im][j];
#pragma unroll
            for (int h = 0; h < 2; h++) {
                int rg = r0g + h * 8;
                if (rg < cnt) {
                    float g = g_gate[base + rg];
                    float2 o;
                    o.x = g * (a[2*h]   + bb.x);
                    o.y = g * (a[2*h+1] + bb.y);
                    *(float2*)(g_partial + (size_t)(base + rg) * DIM + col) = o;
                }
            }
        }
    }
}

// ---------------------------------------------------------------------------
// combine
// ---------------------------------------------------------------------------
__global__ void k_combine(float* __restrict__ out) {
    int idx = blockIdx.x * blockDim.x + threadIdx.x;   // one float4 each
    int t  = idx >> 8;
    int c4 = idx & 255;
    int s0 = g_slot[t * 2];
    int s1 = g_slot[t * 2 + 1];
    float4 a = *(const float4*)(g_partial + (size_t)s0 * DIM + c4 * 4);
    float4 b = *(const float4*)(g_partial + (size_t)s1 * DIM + c4 * 4);
    float4 r;
    r.x = a.x + b.x; r.y = a.y + b.y; r.z = a.z + b.z; r.w = a.w + b.w;
    ((float4*)out)[idx] = r;
}

// ---------------------------------------------------------------------------
extern "C" void kernel_launch(void* const* d_in, const int* in_sizes, int n_in,
                              void* d_out, int out_size) {
    const float* x  = (const float*)d_in[0];
    const float* Wg = (const float*)d_in[1];
    const float* bg = (const float*)d_in[2];
    const float* W1 = (const float*)d_in[3];
    const float* b1 = (const float*)d_in[4];
    const float* W2 = (const float*)d_in[5];
    const float* b2 = (const float*)d_in[6];
    float* out = (float*)d_out;

    const int SMEM1 = 2 * 32768;   // 64 KB
    const int SMEM2 = 2 * 49152;   // 96 KB
    cudaFuncSetAttribute(k_gemm1_mma,
                         cudaFuncAttributeMaxDynamicSharedMemorySize, SMEM1);
    cudaFuncSetAttribute(k_gemm2_mma,
                         cudaFuncAttributeMaxDynamicSharedMemorySize, SMEM2);

    k_init<<<1, 32>>>();
    k_gate<<<TOK / 8, 256>>>(x, Wg, bg);
    k_scan<<<1, 32>>>();
    k_assign<<<TOK / 256, 256>>>();
    k_conv_x<<<(TOK * DIM / 4) / 256, 256>>>(x);
    k_trans_w1<<<dim3(HID / 32, DIM / 32, NEXP), dim3(32, 8)>>>(W1);
    k_trans_w2<<<dim3(DIM / 32, HID / 32, NEXP), dim3(32, 8)>>>(W2);
    k_gemm1_mma<<<dim3(HID / 128, TOK / 128, NEXP), 256, SMEM1>>>(b1);
    k_gemm2_mma<<<dim3(DIM / 128, TOK / 256, NEXP), 512, SMEM2>>>(b2);
    k_combine<<<(TOK * DIM / 4) / 256, 256>>>(out);
}

// round 9
// speedup vs baseline: 1.0691x; 1.0691x over previous
#include <cuda_runtime.h>
#include <cuda_fp16.h>
#include <cstdint>
#include <cstddef>

#define TOK   8192
#define DIM   1024
#define HID   4096
#define NEXP  8

using u32 = uint32_t;

// ---------------------------------------------------------------------------
// device scratch
// ---------------------------------------------------------------------------
__device__ int    g_count[NEXP];
__device__ int    g_base[NEXP];
__device__ int    g_fill[NEXP];
__device__ int    g_topk_idx[TOK * 2];
__device__ float  g_topk_w[TOK * 2];
__device__ int    g_tok[TOK * 2];
__device__ float  g_gate[TOK * 2];
__device__ int    g_slot[TOK * 2];
__device__ __half g_xh[(size_t)TOK * DIM];
__device__ __half g_w1h[(size_t)NEXP * HID * DIM];   // [e][n(HID)][k(DIM)] K-major
__device__ __half g_w2h[(size_t)NEXP * DIM * HID];   // [e][n(DIM)][k(HID)] K-major
__device__ __half g_hid[(size_t)TOK * 2 * HID];
__device__ float  g_partial[(size_t)TOK * 2 * DIM];

// ---------------------------------------------------------------------------
// PTX helpers (baseline PTX ISA: ldmatrix / mma.sync / cp.async)
// ---------------------------------------------------------------------------
__device__ __forceinline__ u32 smem_u32(const void* p) {
    u32 a;
    asm("{ .reg .u64 t; cvta.to.shared.u64 t, %1; cvt.u32.u64 %0, t; }"
        : "=r"(a) : "l"(p));
    return a;
}
__device__ __forceinline__ u32 sw128(u32 off) { return off ^ ((off >> 3) & 0x70); }

__device__ __forceinline__ void cp16(u32 saddr, const void* gptr) {
    asm volatile("cp.async.cg.shared.global [%0], [%1], 16;"
                 :: "r"(saddr), "l"(gptr));
}
#define CP_COMMIT() asm volatile("cp.async.commit_group;" ::: "memory")
#define CP_WAIT1()  asm volatile("cp.async.wait_group 1;" ::: "memory")
#define CP_WAIT0()  asm volatile("cp.async.wait_group 0;" ::: "memory")

__device__ __forceinline__ void ldsm4(u32* r, u32 addr) {
    asm volatile("ldmatrix.sync.aligned.m8n8.x4.shared.b16 {%0,%1,%2,%3}, [%4];"
                 : "=r"(r[0]), "=r"(r[1]), "=r"(r[2]), "=r"(r[3]) : "r"(addr));
}
__device__ __forceinline__ void mma16816(float* d, const u32* a, u32 b0, u32 b1) {
    asm volatile(
        "mma.sync.aligned.m16n8k16.row.col.f32.f16.f16.f32 "
        "{%0,%1,%2,%3}, {%4,%5,%6,%7}, {%8,%9}, {%0,%1,%2,%3};"
        : "+f"(d[0]), "+f"(d[1]), "+f"(d[2]), "+f"(d[3])
        : "r"(a[0]), "r"(a[1]), "r"(a[2]), "r"(a[3]), "r"(b0), "r"(b1));
}

// ---------------------------------------------------------------------------
// gating chain (k_gate also emits x in fp16 — fused conversion)
// ---------------------------------------------------------------------------
__global__ void k_init() { if (threadIdx.x < NEXP) g_count[threadIdx.x] = 0; }

__global__ void k_gate(const float* __restrict__ x,
                       const float* __restrict__ Wg,
                       const float* __restrict__ bg) {
    int warp = (blockIdx.x * blockDim.x + threadIdx.x) >> 5;
    int lane = threadIdx.x & 31;
    if (warp >= TOK) return;
    const float* xp = x + (size_t)warp * DIM;
    uint2* xo = (uint2*)(g_xh + (size_t)warp * DIM);
    float acc[8] = {0,0,0,0,0,0,0,0};
    for (int d0 = lane * 4; d0 < DIM; d0 += 128) {
        float4 v = *(const float4*)(xp + d0);
        __half2 h01 = __halves2half2(__float2half(v.x), __float2half(v.y));
        __half2 h23 = __halves2half2(__float2half(v.z), __float2half(v.w));
        uint2 st;
        st.x = *reinterpret_cast<u32*>(&h01);
        st.y = *reinterpret_cast<u32*>(&h23);
        xo[d0 >> 2] = st;
        float xv[4] = {v.x, v.y, v.z, v.w};
#pragma unroll
        for (int q = 0; q < 4; q++) {
            const float4* w = (const float4*)(Wg + (d0 + q) * 8);
            float4 w0 = w[0], w1 = w[1];
            acc[0] += xv[q] * w0.x; acc[1] += xv[q] * w0.y;
            acc[2] += xv[q] * w0.z; acc[3] += xv[q] * w0.w;
            acc[4] += xv[q] * w1.x; acc[5] += xv[q] * w1.y;
            acc[6] += xv[q] * w1.z; acc[7] += xv[q] * w1.w;
        }
    }
#pragma unroll
    for (int off = 16; off > 0; off >>= 1)
#pragma unroll
        for (int e = 0; e < 8; e++)
            acc[e] += __shfl_xor_sync(0xffffffffu, acc[e], off);
    if (lane == 0) {
        float l[8], m = -1e30f;
#pragma unroll
        for (int e = 0; e < 8; e++) { l[e] = acc[e] + bg[e]; m = fmaxf(m, l[e]); }
        float p[8], s = 0.f;
#pragma unroll
        for (int e = 0; e < 8; e++) { p[e] = expf(l[e] - m); s += p[e]; }
        int i1 = 0;
#pragma unroll
        for (int e = 1; e < 8; e++) if (p[e] > p[i1]) i1 = e;
        int i2 = (i1 == 0) ? 1 : 0;
#pragma unroll
        for (int e = 0; e < 8; e++) if (e != i1 && p[e] > p[i2]) i2 = e;
        float inv = 1.f / s;
        g_topk_idx[warp*2]   = i1; g_topk_w[warp*2]   = p[i1] * inv;
        g_topk_idx[warp*2+1] = i2; g_topk_w[warp*2+1] = p[i2] * inv;
        atomicAdd(&g_count[i1], 1);
        atomicAdd(&g_count[i2], 1);
    }
}

__global__ void k_scan() {
    if (threadIdx.x == 0 && blockIdx.x == 0) {
        int s = 0;
        for (int e = 0; e < NEXP; e++) { g_base[e] = s; s += g_count[e]; g_fill[e] = 0; }
    }
}

__global__ void k_assign() {
    int t = blockIdx.x * blockDim.x + threadIdx.x;
    if (t >= TOK) return;
#pragma unroll
    for (int k = 0; k < 2; k++) {
        int   e = g_topk_idx[t*2 + k];
        float w = g_topk_w[t*2 + k];
        int pos = g_base[e] + atomicAdd(&g_fill[e], 1);
        g_tok[pos]  = t;
        g_gate[pos] = w;
        g_slot[t*2 + k] = pos;
    }
}

// ---------------------------------------------------------------------------
// weight transpose + fp16 convert: tile 64(k) x 32(n), half2 stores (128B rows
// both directions). block (32,8).
// ---------------------------------------------------------------------------
__device__ __forceinline__ void trans_body(const float* __restrict__ W,
                                           __half* __restrict__ Wh,
                                           int KD, int ND) {
    __shared__ float s[64][33];
    int e  = blockIdx.z;
    int n0 = blockIdx.x * 32, k0 = blockIdx.y * 64;
    int tx = threadIdx.x, ty = threadIdx.y;           // 32 x 8
    const float* Wp = W + (size_t)e * KD * ND;
    // load 64 k-rows x 32 n-cols (each row: 32 floats = 128B)
#pragma unroll
    for (int j = 0; j < 8; j++)
        s[ty + 8*j][tx] = Wp[(size_t)(k0 + ty + 8*j) * ND + n0 + tx];
    __syncthreads();
    // store 32 n-rows x 64 k (each lane: half2 at k=2tx -> row of 32x4B=128B)
    size_t ob = (size_t)e * ND * KD;
#pragma unroll
    for (int j = 0; j < 4; j++) {
        int n = ty + 8*j;
        float v0 = s[2*tx]
                    [n];
        float v1 = s[2*tx + 1][n];
        __half2 h = __halves2half2(__float2half(v0), __float2half(v1));
        *(__half2*)(Wh + ob + (size_t)(n0 + n) * KD + k0 + 2*tx) = h;
    }
}
__global__ void k_trans_w1(const float* __restrict__ W) { trans_body(W, g_w1h, DIM, HID); }
__global__ void k_trans_w2(const float* __restrict__ W) { trans_body(W, g_w2h, HID, DIM); }

// ---------------------------------------------------------------------------
// grouped fp16 HMMA GEMM (exact R6 config): CTA 128x128, KC=64, 2-stage,
// 256 thr, 2 CTAs/SM; warp layout 4(m) x 2(n); warp tile 32x64
// smem stage: [Ah 16K][Bh 16K] = 32KB, 2 stages = 64KB
// ---------------------------------------------------------------------------
template<int KDIM, bool IS_G1>
__global__ __launch_bounds__(256, 2) void k_gemm_mma(const float* __restrict__ bias_all) {
    constexpr int NC  = KDIM / 64;
    constexpr int NDIM_ = IS_G1 ? HID : DIM;
    constexpr int STG = 32768;
    constexpr int AH = 0, BH = 16384;

    const int e    = blockIdx.z;
    const int cnt  = g_count[e];
    const int row0 = blockIdx.y * 128;
    if (row0 >= cnt) return;
    const int base = g_base[e];
    const int n0   = blockIdx.x * 128;

    const __half* __restrict__ Ah = IS_G1 ? g_xh : g_hid;
    const __half* __restrict__ Bh = (IS_G1 ? g_w1h : g_w2h) + (size_t)e * NDIM_ * KDIM;
    const float* __restrict__ bias = bias_all + (size_t)e * NDIM_;

    extern __shared__ char smem[];
    const u32 sbase = smem_u32(smem);
    const int tid = threadIdx.x, wid = tid >> 5, lane = tid & 31;
    const int warp_m = wid & 3, warp_n = wid >> 2;

    const int lane8 = tid & 7, r32 = tid >> 3;
    int aoff[4], boff[4];
    u32 sAB[4];
#pragma unroll
    for (int i = 0; i < 4; i++) {
        int ridx = r32 + 32 * i;
        int rc = min(row0 + ridx, cnt - 1);
        aoff[i] = IS_G1 ? (g_tok[base + rc] * DIM) : ((base + rc) * HID);
        boff[i] = (n0 + ridx) * KDIM;
        sAB[i]  = sw128((u32)(ridx * 128 + lane8 * 16));
    }

    float acc[2][8][4];
#pragma unroll
    for (int im = 0; im < 2; im++)
#pragma unroll
        for (int j = 0; j < 8; j++)
#pragma unroll
            for (int q = 0; q < 4; q++) acc[im][j][q] = 0.f;

    const int lrow = (lane & 7) + ((lane >> 3) & 1) * 8;
    u32 rowA[2], rowB[4];
#pragma unroll
    for (int im = 0; im < 2; im++)
        rowA[im] = (u32)((warp_m * 32 + im * 16 + lrow) * 128);
#pragma unroll
    for (int p = 0; p < 4; p++)
        rowB[p] = (u32)((warp_n * 64 + p * 16 + lrow) * 128);
    const u32 bcolbase = ((lane >> 4) & 1) * 16;

    auto issue = [&](int ic) {
        const int co = ic * 64 + lane8 * 8;
        const u32 st = sbase + (u32)((ic & 1) * STG);
#pragma unroll
        for (int i = 0; i < 4; i++) {
            cp16(st + AH + sAB[i], Ah + aoff[i] + co);
            cp16(st + BH + sAB[i], Bh + boff[i] + co);
        }
        CP_COMMIT();
    };

    issue(0);
#pragma unroll 1
    for (int ic = 0; ic < NC; ic++) {
        if (ic + 1 < NC) { issue(ic + 1); CP_WAIT1(); }
        else             { CP_WAIT0(); }
        __syncthreads();
        const u32 st = sbase + (u32)((ic & 1) * STG);
#pragma unroll
        for (int s = 0; s < 4; s++) {
            const u32 bcol = (u32)(s * 32) + bcolbase;
            u32 a_h[2][4];
#pragma unroll
            for (int im = 0; im < 2; im++)
                ldsm4(a_h[im], st + AH + sw128(rowA[im] + bcol));
#pragma unroll
            for (int p = 0; p < 4; p++) {
                u32 b_h[4];
                ldsm4(b_h, st + BH + sw128(rowB[p] + bcol));
#pragma unroll
                for (int im = 0; im < 2; im++) {
                    mma16816(acc[im][2*p],   a_h[im], b_h[0], b_h[2]);
                    mma16816(acc[im][2*p+1], a_h[im], b_h[1], b_h[3]);
                }
            }
        }
        __syncthreads();
    }

    const int crow = lane >> 2;          // 0..7
    const int ccol = (lane & 3) * 2;     // 0,2,4,6
#pragma unroll
    for (int im = 0; im < 2; im++) {
#pragma unroll
        for (int j = 0; j < 8; j++) {
            const int p = j >> 1, q = j & 1;
            const int col = n0 + warp_n * 64 + p * 16 + q * 8 + ccol;
            const float2 bb = *(const float2*)(bias + col);
            const int r0g = row0 + warp_m * 32 + im * 16 + crow;
            float* a = acc[im][j];
            if (IS_G1) {
#pragma unroll
                for (int h = 0; h < 2; h++) {
                    int rg = r0g + h * 8;
                    if (rg < cnt) {
                        float v0 = fmaxf(a[2*h]   + bb.x, 0.f);
                        float v1 = fmaxf(a[2*h+1] + bb.y, 0.f);
                        __half2 ph = __halves2half2(__float2half(v0), __float2half(v1));
                        size_t o = (size_t)(base + rg) * HID + col;
                        *(u32*)(g_hid + o) = *reinterpret_cast<u32*>(&ph);
                    }
                }
            } else {
#pragma unroll
                for (int h = 0; h < 2; h++) {
                    int rg = r0g + h * 8;
                    if (rg < cnt) {
                        float g = g_gate[base + rg];
                        float2 o;
                        o.x = g * (a[2*h]   + bb.x);
                        o.y = g * (a[2*h+1] + bb.y);
                        *(float2*)(g_partial + (size_t)(base + rg) * DIM + col) = o;
                    }
                }
            }
        }
    }
}

// ---------------------------------------------------------------------------
// combine
// ---------------------------------------------------------------------------
__global__ void k_combine(float* __restrict__ out) {
    int idx = blockIdx.x * blockDim.x + threadIdx.x;   // one float4 each
    int t  = idx >> 8;
    int c4 = idx & 255;
    int s0 = g_slot[t * 2];
    int s1 = g_slot[t * 2 + 1];
    float4 a = *(const float4*)(g_partial + (size_t)s0 * DIM + c4 * 4);
    float4 b = *(const float4*)(g_partial + (size_t)s1 * DIM + c4 * 4);
    float4 r;
    r.x = a.x + b.x; r.y = a.y + b.y; r.z = a.z + b.z; r.w = a.w + b.w;
    ((float4*)out)[idx] = r;
}

// ---------------------------------------------------------------------------
extern "C" void kernel_launch(void* const* d_in, const int* in_sizes, int n_in,
                              void* d_out, int out_size) {
    const float* x  = (const float*)d_in[0];
    const float* Wg = (const float*)d_in[1];
    const float* bg = (const float*)d_in[2];
    const float* W1 = (const float*)d_in[3];
    const float* b1 = (const float*)d_in[4];
    const float* W2 = (const float*)d_in[5];
    const float* b2 = (const float*)d_in[6];
    float* out = (float*)d_out;

    const int SMEM_SZ = 2 * 32768;   // 64 KB
    cudaFuncSetAttribute(k_gemm_mma<DIM, true>,
                         cudaFuncAttributeMaxDynamicSharedMemorySize, SMEM_SZ);
    cudaFuncSetAttribute(k_gemm_mma<HID, false>,
                         cudaFuncAttributeMaxDynamicSharedMemorySize, SMEM_SZ);

    k_init<<<1, 32>>>();
    k_gate<<<TOK / 8, 256>>>(x, Wg, bg);
    k_scan<<<1, 32>>>();
    k_assign<<<TOK / 256, 256>>>();
    k_trans_w1<<<dim3(HID / 32, DIM / 64, NEXP), dim3(32, 8)>>>(W1);
    k_trans_w2<<<dim3(DIM / 32, HID / 64, NEXP), dim3(32, 8)>>>(W2);
    k_gemm_mma<DIM, true ><<<dim3(HID / 128, TOK / 128, NEXP), 256, SMEM_SZ>>>(b1);
    k_gemm_mma<HID, false><<<dim3(DIM / 128, TOK / 128, NEXP), 256, SMEM_SZ>>>(b2);
    k_combine<<<(TOK * DIM / 4) / 256, 256>>>(out);
}

// round 10
// speedup vs baseline: 1.1127x; 1.0408x over previous
#include <cuda_runtime.h>
#include <cuda_fp16.h>
#include <cstdint>
#include <cstddef>

#define TOK   8192
#define DIM   1024
#define HID   4096
#define NEXP  8

using u32 = uint32_t;

// ---------------------------------------------------------------------------
// device scratch
// ---------------------------------------------------------------------------
__device__ int    g_count[NEXP];
__device__ int    g_fill[NEXP];
__device__ int    g_topk_idx[TOK * 2];
__device__ float  g_topk_w[TOK * 2];
__device__ int    g_tok[TOK * 2];
__device__ float  g_gate[TOK * 2];
__device__ int    g_slot[TOK * 2];
__device__ __half g_xh[(size_t)TOK * DIM];
__device__ __half g_w1h[(size_t)NEXP * HID * DIM];   // [e][n(HID)][k(DIM)] K-major
__device__ __half g_w2h[(size_t)NEXP * DIM * HID];   // [e][n(DIM)][k(HID)] K-major
__device__ __half g_hid[(size_t)TOK * 2 * HID];
__device__ float  g_partial[(size_t)TOK * 2 * DIM];

// ---------------------------------------------------------------------------
// PTX helpers (baseline PTX ISA: ldmatrix / mma.sync / cp.async)
// ---------------------------------------------------------------------------
__device__ __forceinline__ u32 smem_u32(const void* p) {
    u32 a;
    asm("{ .reg .u64 t; cvta.to.shared.u64 t, %1; cvt.u32.u64 %0, t; }"
        : "=r"(a) : "l"(p));
    return a;
}
__device__ __forceinline__ u32 sw128(u32 off) { return off ^ ((off >> 3) & 0x70); }

__device__ __forceinline__ void cp16(u32 saddr, const void* gptr) {
    asm volatile("cp.async.cg.shared.global [%0], [%1], 16;"
                 :: "r"(saddr), "l"(gptr));
}
#define CP_COMMIT() asm volatile("cp.async.commit_group;" ::: "memory")
#define CP_WAIT1()  asm volatile("cp.async.wait_group 1;" ::: "memory")
#define CP_WAIT0()  asm volatile("cp.async.wait_group 0;" ::: "memory")

__device__ __forceinline__ void ldsm4(u32* r, u32 addr) {
    asm volatile("ldmatrix.sync.aligned.m8n8.x4.shared.b16 {%0,%1,%2,%3}, [%4];"
                 : "=r"(r[0]), "=r"(r[1]), "=r"(r[2]), "=r"(r[3]) : "r"(addr));
}
__device__ __forceinline__ void mma16816(float* d, const u32* a, u32 b0, u32 b1) {
    asm volatile(
        "mma.sync.aligned.m16n8k16.row.col.f32.f16.f16.f32 "
        "{%0,%1,%2,%3}, {%4,%5,%6,%7}, {%8,%9}, {%0,%1,%2,%3};"
        : "+f"(d[0]), "+f"(d[1]), "+f"(d[2]), "+f"(d[3])
        : "r"(a[0]), "r"(a[1]), "r"(a[2]), "r"(a[3]), "r"(b0), "r"(b1));
}

// ---------------------------------------------------------------------------
// gating chain
// ---------------------------------------------------------------------------
__global__ void k_init() {
    if (threadIdx.x < NEXP) { g_count[threadIdx.x] = 0; g_fill[threadIdx.x] = 0; }
}

__global__ void k_gate(const float* __restrict__ x,
                       const float* __restrict__ Wg,
                       const float* __restrict__ bg) {
    int warp = (blockIdx.x * blockDim.x + threadIdx.x) >> 5;
    int lane = threadIdx.x & 31;
    if (warp >= TOK) return;
    const float* xp = x + (size_t)warp * DIM;
    float acc[8] = {0,0,0,0,0,0,0,0};
    for (int d = lane; d < DIM; d += 32) {
        float xv = xp[d];
        const float4* w = (const float4*)(Wg + d * 8);
        float4 w0 = w[0], w1 = w[1];
        acc[0] += xv * w0.x; acc[1] += xv * w0.y;
        acc[2] += xv * w0.z; acc[3] += xv * w0.w;
        acc[4] += xv * w1.x; acc[5] += xv * w1.y;
        acc[6] += xv * w1.z; acc[7] += xv * w1.w;
    }
#pragma unroll
    for (int off = 16; off > 0; off >>= 1)
#pragma unroll
        for (int e = 0; e < 8; e++)
            acc[e] += __shfl_xor_sync(0xffffffffu, acc[e], off);
    if (lane == 0) {
        float l[8], m = -1e30f;
#pragma unroll
        for (int e = 0; e < 8; e++) { l[e] = acc[e] + bg[e]; m = fmaxf(m, l[e]); }
        float p[8], s = 0.f;
#pragma unroll
        for (int e = 0; e < 8; e++) { p[e] = expf(l[e] - m); s += p[e]; }
        int i1 = 0;
#pragma unroll
        for (int e = 1; e < 8; e++) if (p[e] > p[i1]) i1 = e;
        int i2 = (i1 == 0) ? 1 : 0;
#pragma unroll
        for (int e = 0; e < 8; e++) if (e != i1 && p[e] > p[i2]) i2 = e;
        float inv = 1.f / s;
        g_topk_idx[warp*2]   = i1; g_topk_w[warp*2]   = p[i1] * inv;
        g_topk_idx[warp*2+1] = i2; g_topk_w[warp*2+1] = p[i2] * inv;
        atomicAdd(&g_count[i1], 1);
        atomicAdd(&g_count[i2], 1);
    }
}

// assign computes the 8-wide prefix sum locally (counts are L2-hot) — the
// separate single-thread scan kernel is deleted.
__global__ void k_assign() {
    int t = blockIdx.x * blockDim.x + threadIdx.x;
    if (t >= TOK) return;
    int cnt[NEXP], pre[NEXP];
    int s = 0;
#pragma unroll
    for (int e = 0; e < NEXP; e++) { cnt[e] = g_count[e]; pre[e] = s; s += cnt[e]; }
#pragma unroll
    for (int k = 0; k < 2; k++) {
        int   e = g_topk_idx[t*2 + k];
        float w = g_topk_w[t*2 + k];
        int pos = pre[e] + atomicAdd(&g_fill[e], 1);
        g_tok[pos]  = t;
        g_gate[pos] = w;
        g_slot[t*2 + k] = pos;
    }
}

// ---------------------------------------------------------------------------
// conversion prepasses: x -> fp16; W -> transposed (K-major) fp16
// ---------------------------------------------------------------------------
__global__ void k_conv_x(const float* __restrict__ x) {
    int i = blockIdx.x * blockDim.x + threadIdx.x;   // one float4 each
    float4 v = ((const float4*)x)[i];
    __half2* ph = (__half2*)g_xh;
    ph[2*i]   = __halves2half2(__float2half(v.x), __float2half(v.y));
    ph[2*i+1] = __halves2half2(__float2half(v.z), __float2half(v.w));
}

// tile 64(k) x 32(n), half2 stores — full 128B transactions both directions
__device__ __forceinline__ void trans_body(const float* __restrict__ W,
                                           __half* __restrict__ Wh,
                                           int KD, int ND) {
    __shared__ float s[64][33];
    int e  = blockIdx.z;
    int n0 = blockIdx.x * 32, k0 = blockIdx.y * 64;
    int tx = threadIdx.x, ty = threadIdx.y;           // 32 x 8
    const float* Wp = W + (size_t)e * KD * ND;
#pragma unroll
    for (int j = 0; j < 8; j++)
        s[ty + 8*j][tx] = Wp[(size_t)(k0 + ty + 8*j) * ND + n0 + tx];
    __syncthreads();
    size_t ob = (size_t)e * ND * KD;
#pragma unroll
    for (int j = 0; j < 4; j++) {
        int n = ty + 8*j;
        float v0 = s[2*tx][n];
        float v1 = s[2*tx + 1][n];
        __half2 h = __halves2half2(__float2half(v0), __float2half(v1));
        *(__half2*)(Wh + ob + (size_t)(n0 + n) * KD + k0 + 2*tx) = h;
    }
}
__global__ void k_trans_w1(const float* __restrict__ W) { trans_body(W, g_w1h, DIM, HID); }
__global__ void k_trans_w2(const float* __restrict__ W) { trans_body(W, g_w2h, HID, DIM); }

// ---------------------------------------------------------------------------
// grouped fp16 HMMA GEMM (exact R6 config): CTA 128x128, KC=64, 2-stage,
// 256 thr, 2 CTAs/SM; warp layout 4(m) x 2(n); warp tile 32x64
// smem stage: [Ah 16K][Bh 16K] = 32KB, 2 stages = 64KB
// ---------------------------------------------------------------------------
template<int KDIM, bool IS_G1>
__global__ __launch_bounds__(256, 2) void k_gemm_mma(const float* __restrict__ bias_all) {
    constexpr int NC  = KDIM / 64;
    constexpr int NDIM_ = IS_G1 ? HID : DIM;
    constexpr int STG = 32768;
    constexpr int AH = 0, BH = 16384;

    const int e    = blockIdx.z;
    const int cnt  = g_count[e];
    const int row0 = blockIdx.y * 128;
    if (row0 >= cnt) return;
    int base = 0;
#pragma unroll
    for (int q = 0; q < NEXP; q++) base += (q < e) ? g_count[q] : 0;
    const int n0   = blockIdx.x * 128;

    const __half* __restrict__ Ah = IS_G1 ? g_xh : g_hid;
    const __half* __restrict__ Bh = (IS_G1 ? g_w1h : g_w2h) + (size_t)e * NDIM_ * KDIM;
    const float* __restrict__ bias = bias_all + (size_t)e * NDIM_;

    extern __shared__ char smem[];
    const u32 sbase = smem_u32(smem);
    const int tid = threadIdx.x, wid = tid >> 5, lane = tid & 31;
    const int warp_m = wid & 3, warp_n = wid >> 2;

    const int lane8 = tid & 7, r32 = tid >> 3;
    int aoff[4], boff[4];
    u32 sAB[4];
#pragma unroll
    for (int i = 0; i < 4; i++) {
        int ridx = r32 + 32 * i;
        int rc = min(row0 + ridx, cnt - 1);
        aoff[i] = IS_G1 ? (g_tok[base + rc] * DIM) : ((base + rc) * HID);
        boff[i] = (n0 + ridx) * KDIM;
        sAB[i]  = sw128((u32)(ridx * 128 + lane8 * 16));
    }

    float acc[2][8][4];
#pragma unroll
    for (int im = 0; im < 2; im++)
#pragma unroll
        for (int j = 0; j < 8; j++)
#pragma unroll
            for (int q = 0; q < 4; q++) acc[im][j][q] = 0.f;

    const int lrow = (lane & 7) + ((lane >> 3) & 1) * 8;
    u32 rowA[2], rowB[4];
#pragma unroll
    for (int im = 0; im < 2; im++)
        rowA[im] = (u32)((warp_m * 32 + im * 16 + lrow) * 128);
#pragma unroll
    for (int p = 0; p < 4; p++)
        rowB[p] = (u32)((warp_n * 64 + p * 16 + lrow) * 128);
    const u32 bcolbase = ((lane >> 4) & 1) * 16;

    auto issue = [&](int ic) {
        const int co = ic * 64 + lane8 * 8;
        const u32 st = sbase + (u32)((ic & 1) * STG);
#pragma unroll
        for (int i = 0; i < 4; i++) {
            cp16(st + AH + sAB[i], Ah + aoff[i] + co);
            cp16(st + BH + sAB[i], Bh + boff[i] + co);
        }
        CP_COMMIT();
    };

    issue(0);
#pragma unroll 1
    for (int ic = 0; ic < NC; ic++) {
        if (ic + 1 < NC) { issue(ic + 1); CP_WAIT1(); }
        else             { CP_WAIT0(); }
        __syncthreads();
        const u32 st = sbase + (u32)((ic & 1) * STG);
#pragma unroll
        for (int s = 0; s < 4; s++) {
            const u32 bcol = (u32)(s * 32) + bcolbase;
            u32 a_h[2][4];
#pragma unroll
            for (int im = 0; im < 2; im++)
                ldsm4(a_h[im], st + AH + sw128(rowA[im] + bcol));
#pragma unroll
            for (int p = 0; p < 4; p++) {
                u32 b_h[4];
                ldsm4(b_h, st + BH + sw128(rowB[p] + bcol));
#pragma unroll
                for (int im = 0; im < 2; im++) {
                    mma16816(acc[im][2*p],   a_h[im], b_h[0], b_h[2]);
                    mma16816(acc[im][2*p+1], a_h[im], b_h[1], b_h[3]);
                }
            }
        }
        __syncthreads();
    }

    const int crow = lane >> 2;          // 0..7
    const int ccol = (lane & 3) * 2;     // 0,2,4,6
#pragma unroll
    for (int im = 0; im < 2; im++) {
#pragma unroll
        for (int j = 0; j < 8; j++) {
            const int p = j >> 1, q = j & 1;
            const int col = n0 + warp_n * 64 + p * 16 + q * 8 + ccol;
            const float2 bb = *(const float2*)(bias + col);
            const int r0g = row0 + warp_m * 32 + im * 16 + crow;
            float* a = acc[im][j];
            if (IS_G1) {
#pragma unroll
                for (int h = 0; h < 2; h++) {
                    int rg = r0g + h * 8;
                    if (rg < cnt) {
                        float v0 = fmaxf(a[2*h]   + bb.x, 0.f);
                        float v1 = fmaxf(a[2*h+1] + bb.y, 0.f);
                        __half2 ph = __halves2half2(__float2half(v0), __float2half(v1));
                        size_t o = (size_t)(base + rg) * HID + col;
                        *(u32*)(g_hid + o) = *reinterpret_cast<u32*>(&ph);
                    }
                }
            } else {
#pragma unroll
                for (int h = 0; h < 2; h++) {
                    int rg = r0g + h * 8;
                    if (rg < cnt) {
                        float g = g_gate[base + rg];
                        float2 o;
                        o.x = g * (a[2*h]   + bb.x);
                        o.y = g * (a[2*h+1] + bb.y);
                        *(float2*)(g_partial + (size_t)(base + rg) * DIM + col) = o;
                    }
                }
            }
        }
    }
}

// ---------------------------------------------------------------------------
// combine
// ---------------------------------------------------------------------------
__global__ void k_combine(float* __restrict__ out) {
    int idx = blockIdx.x * blockDim.x + threadIdx.x;   // one float4 each
    int t  = idx >> 8;
    int c4 = idx & 255;
    int s0 = g_slot[t * 2];
    int s1 = g_slot[t * 2 + 1];
    float4 a = *(const float4*)(g_partial + (size_t)s0 * DIM + c4 * 4);
    float4 b = *(const float4*)(g_partial + (size_t)s1 * DIM + c4 * 4);
    float4 r;
    r.x = a.x + b.x; r.y = a.y + b.y; r.z = a.z + b.z; r.w = a.w + b.w;
    ((float4*)out)[idx] = r;
}

// ---------------------------------------------------------------------------
extern "C" void kernel_launch(void* const* d_in, const int* in_sizes, int n_in,
                              void* d_out, int out_size) {
    const float* x  = (const float*)d_in[0];
    const float* Wg = (const float*)d_in[1];
    const float* bg = (const float*)d_in[2];
    const float* W1 = (const float*)d_in[3];
    const float* b1 = (const float*)d_in[4];
    const float* W2 = (const float*)d_in[5];
    const float* b2 = (const float*)d_in[6];
    float* out = (float*)d_out;

    const int SMEM_SZ = 2 * 32768;   // 64 KB
    cudaFuncSetAttribute(k_gemm_mma<DIM, true>,
                         cudaFuncAttributeMaxDynamicSharedMemorySize, SMEM_SZ);
    cudaFuncSetAttribute(k_gemm_mma<HID, false>,
                         cudaFuncAttributeMaxDynamicSharedMemorySize, SMEM_SZ);

    k_init<<<1, 32>>>();
    k_gate<<<TOK / 8, 256>>>(x, Wg, bg);
    k_assign<<<TOK / 256, 256>>>();
    k_conv_x<<<(TOK * DIM / 4) / 256, 256>>>(x);
    k_trans_w1<<<dim3(HID / 32, DIM / 64, NEXP), dim3(32, 8)>>>(W1);
    k_trans_w2<<<dim3(DIM / 32, HID / 64, NEXP), dim3(32, 8)>>>(W2);
    k_gemm_mma<DIM, true ><<<dim3(HID / 128, TOK / 128, NEXP), 256, SMEM_SZ>>>(b1);
    k_gemm_mma<HID, false><<<dim3(DIM / 128, TOK / 128, NEXP), 256, SMEM_SZ>>>(b2);
    k_combine<<<(TOK * DIM / 4) / 256, 256>>>(out);
}

// round 11
// speedup vs baseline: 1.1130x; 1.0003x over previous
#include <cuda_runtime.h>
#include <cuda_fp16.h>
#include <cstdint>
#include <cstddef>

#define TOK   8192
#define DIM   1024
#define HID   4096
#define NEXP  8

using u32 = uint32_t;

// ---------------------------------------------------------------------------
// device scratch
// ---------------------------------------------------------------------------
__device__ int    g_cnt2[2 * NEXP];     // [0..7]=count, [8..15]=fill (one memset)
__device__ int    g_topk_idx[TOK * 2];
__device__ float  g_topk_w[TOK * 2];
__device__ int    g_tok[TOK * 2];
__device__ float  g_gate[TOK * 2];
__device__ __half g_xh[(size_t)TOK * DIM];
__device__ __half g_w1h[(size_t)NEXP * HID * DIM];   // [e][n(HID)][k(DIM)] K-major
__device__ __half g_w2h[(size_t)NEXP * DIM * HID];   // [e][n(DIM)][k(HID)] K-major
__device__ __half g_hid[(size_t)TOK * 2 * HID];

// ---------------------------------------------------------------------------
// PTX helpers (baseline PTX ISA: ldmatrix / mma.sync / cp.async)
// ---------------------------------------------------------------------------
__device__ __forceinline__ u32 smem_u32(const void* p) {
    u32 a;
    asm("{ .reg .u64 t; cvta.to.shared.u64 t, %1; cvt.u32.u64 %0, t; }"
        : "=r"(a) : "l"(p));
    return a;
}
__device__ __forceinline__ u32 sw128(u32 off) { return off ^ ((off >> 3) & 0x70); }

__device__ __forceinline__ void cp16(u32 saddr, const void* gptr) {
    asm volatile("cp.async.cg.shared.global [%0], [%1], 16;"
                 :: "r"(saddr), "l"(gptr));
}
#define CP_COMMIT() asm volatile("cp.async.commit_group;" ::: "memory")
#define CP_WAIT1()  asm volatile("cp.async.wait_group 1;" ::: "memory")
#define CP_WAIT0()  asm volatile("cp.async.wait_group 0;" ::: "memory")

__device__ __forceinline__ void ldsm4(u32* r, u32 addr) {
    asm volatile("ldmatrix.sync.aligned.m8n8.x4.shared.b16 {%0,%1,%2,%3}, [%4];"
                 : "=r"(r[0]), "=r"(r[1]), "=r"(r[2]), "=r"(r[3]) : "r"(addr));
}
__device__ __forceinline__ void mma16816(float* d, const u32* a, u32 b0, u32 b1) {
    asm volatile(
        "mma.sync.aligned.m16n8k16.row.col.f32.f16.f16.f32 "
        "{%0,%1,%2,%3}, {%4,%5,%6,%7}, {%8,%9}, {%0,%1,%2,%3};"
        : "+f"(d[0]), "+f"(d[1]), "+f"(d[2]), "+f"(d[3])
        : "r"(a[0]), "r"(a[1]), "r"(a[2]), "r"(a[3]), "r"(b0), "r"(b1));
}

// ---------------------------------------------------------------------------
// gating chain
// ---------------------------------------------------------------------------
__global__ void k_gate(const float* __restrict__ x,
                       const float* __restrict__ Wg,
                       const float* __restrict__ bg) {
    int warp = (blockIdx.x * blockDim.x + threadIdx.x) >> 5;
    int lane = threadIdx.x & 31;
    if (warp >= TOK) return;
    const float* xp = x + (size_t)warp * DIM;
    float acc[8] = {0,0,0,0,0,0,0,0};
    for (int d = lane; d < DIM; d += 32) {
        float xv = xp[d];
        const float4* w = (const float4*)(Wg + d * 8);
        float4 w0 = w[0], w1 = w[1];
        acc[0] += xv * w0.x; acc[1] += xv * w0.y;
        acc[2] += xv * w0.z; acc[3] += xv * w0.w;
        acc[4] += xv * w1.x; acc[5] += xv * w1.y;
        acc[6] += xv * w1.z; acc[7] += xv * w1.w;
    }
#pragma unroll
    for (int off = 16; off > 0; off >>= 1)
#pragma unroll
        for (int e = 0; e < 8; e++)
            acc[e] += __shfl_xor_sync(0xffffffffu, acc[e], off);
    if (lane == 0) {
        float l[8], m = -1e30f;
#pragma unroll
        for (int e = 0; e < 8; e++) { l[e] = acc[e] + bg[e]; m = fmaxf(m, l[e]); }
        float p[8], s = 0.f;
#pragma unroll
        for (int e = 0; e < 8; e++) { p[e] = expf(l[e] - m); s += p[e]; }
        int i1 = 0;
#pragma unroll
        for (int e = 1; e < 8; e++) if (p[e] > p[i1]) i1 = e;
        int i2 = (i1 == 0) ? 1 : 0;
#pragma unroll
        for (int e = 0; e < 8; e++) if (e != i1 && p[e] > p[i2]) i2 = e;
        float inv = 1.f / s;
        g_topk_idx[warp*2]   = i1; g_topk_w[warp*2]   = p[i1] * inv;
        g_topk_idx[warp*2+1] = i2; g_topk_w[warp*2+1] = p[i2] * inv;
        atomicAdd(&g_cnt2[i1], 1);
        atomicAdd(&g_cnt2[i2], 1);
    }
}

// assign computes the 8-wide prefix sum locally (counts are L2-hot)
__global__ void k_assign() {
    int t = blockIdx.x * blockDim.x + threadIdx.x;
    if (t >= TOK) return;
    int pre[NEXP];
    int s = 0;
#pragma unroll
    for (int e = 0; e < NEXP; e++) { pre[e] = s; s += g_cnt2[e]; }
#pragma unroll
    for (int k = 0; k < 2; k++) {
        int   e = g_topk_idx[t*2 + k];
        float w = g_topk_w[t*2 + k];
        int pos = pre[e] + atomicAdd(&g_cnt2[NEXP + e], 1);
        g_tok[pos]  = t;
        g_gate[pos] = w;
    }
}

// ---------------------------------------------------------------------------
// conversion prepasses: x -> fp16; W -> transposed (K-major) fp16
// ---------------------------------------------------------------------------
__global__ void k_conv_x(const float* __restrict__ x) {
    int i = blockIdx.x * blockDim.x + threadIdx.x;   // one float4 each
    float4 v = ((const float4*)x)[i];
    __half2* ph = (__half2*)g_xh;
    ph[2*i]   = __halves2half2(__float2half(v.x), __float2half(v.y));
    ph[2*i+1] = __halves2half2(__float2half(v.z), __float2half(v.w));
}

// tile 64(k) x 32(n), half2 stores — full 128B transactions both directions
__device__ __forceinline__ void trans_body(const float* __restrict__ W,
                                           __half* __restrict__ Wh,
                                           int KD, int ND) {
    __shared__ float s[64][33];
    int e  = blockIdx.z;
    int n0 = blockIdx.x * 32, k0 = blockIdx.y * 64;
    int tx = threadIdx.x, ty = threadIdx.y;           // 32 x 8
    const float* Wp = W + (size_t)e * KD * ND;
#pragma unroll
    for (int j = 0; j < 8; j++)
        s[ty + 8*j][tx] = Wp[(size_t)(k0 + ty + 8*j) * ND + n0 + tx];
    __syncthreads();
    size_t ob = (size_t)e * ND * KD;
#pragma unroll
    for (int j = 0; j < 4; j++) {
        int n = ty + 8*j;
        float v0 = s[2*tx][n];
        float v1 = s[2*tx + 1][n];
        __half2 h = __halves2half2(__float2half(v0), __float2half(v1));
        *(__half2*)(Wh + ob + (size_t)(n0 + n) * KD + k0 + 2*tx) = h;
    }
}
__global__ void k_trans_w1(const float* __restrict__ W) { trans_body(W, g_w1h, DIM, HID); }
__global__ void k_trans_w2(const float* __restrict__ W) { trans_body(W, g_w2h, HID, DIM); }

// ---------------------------------------------------------------------------
// grouped fp16 HMMA GEMM (R6 config): CTA 128x128, KC=64, 2-stage,
// 256 thr, 2 CTAs/SM; warp layout 4(m) x 2(n); warp tile 32x64
// GEMM2 epilogue scatters directly into out via RED.F32 (exactly 2 addends
// per element -> commutative fp add -> bitwise deterministic).
// ---------------------------------------------------------------------------
template<int KDIM, bool IS_G1>
__global__ __launch_bounds__(256, 2) void k_gemm_mma(const float* __restrict__ bias_all,
                                                     float* __restrict__ outp) {
    constexpr int NC  = KDIM / 64;
    constexpr int NDIM_ = IS_G1 ? HID : DIM;
    constexpr int STG = 32768;
    constexpr int AH = 0, BH = 16384;

    const int e    = blockIdx.z;
    const int cnt  = g_cnt2[e];
    const int row0 = blockIdx.y * 128;
    if (row0 >= cnt) return;
    int base = 0;
#pragma unroll
    for (int q = 0; q < NEXP; q++) base += (q < e) ? g_cnt2[q] : 0;
    const int n0   = blockIdx.x * 128;

    const __half* __restrict__ Ah = IS_G1 ? g_xh : g_hid;
    const __half* __restrict__ Bh = (IS_G1 ? g_w1h : g_w2h) + (size_t)e * NDIM_ * KDIM;
    const float* __restrict__ bias = bias_all + (size_t)e * NDIM_;

    extern __shared__ char smem[];
    const u32 sbase = smem_u32(smem);
    const int tid = threadIdx.x, wid = tid >> 5, lane = tid & 31;
    const int warp_m = wid & 3, warp_n = wid >> 2;

    const int lane8 = tid & 7, r32 = tid >> 3;
    int aoff[4], boff[4];
    u32 sAB[4];
#pragma unroll
    for (int i = 0; i < 4; i++) {
        int ridx = r32 + 32 * i;
        int rc = min(row0 + ridx, cnt - 1);
        aoff[i] = IS_G1 ? (g_tok[base + rc] * DIM) : ((base + rc) * HID);
        boff[i] = (n0 + ridx) * KDIM;
        sAB[i]  = sw128((u32)(ridx * 128 + lane8 * 16));
    }

    float acc[2][8][4];
#pragma unroll
    for (int im = 0; im < 2; im++)
#pragma unroll
        for (int j = 0; j < 8; j++)
#pragma unroll
            for (int q = 0; q < 4; q++) acc[im][j][q] = 0.f;

    const int lrow = (lane & 7) + ((lane >> 3) & 1) * 8;
    u32 rowA[2], rowB[4];
#pragma unroll
    for (int im = 0; im < 2; im++)
        rowA[im] = (u32)((warp_m * 32 + im * 16 + lrow) * 128);
#pragma unroll
    for (int p = 0; p < 4; p++)
        rowB[p] = (u32)((warp_n * 64 + p * 16 + lrow) * 128);
    const u32 bcolbase = ((lane >> 4) & 1) * 16;

    auto issue = [&](int ic) {
        const int co = ic * 64 + lane8 * 8;
        const u32 st = sbase + (u32)((ic & 1) * STG);
#pragma unroll
        for (int i = 0; i < 4; i++) {
            cp16(st + AH + sAB[i], Ah + aoff[i] + co);
            cp16(st + BH + sAB[i], Bh + boff[i] + co);
        }
        CP_COMMIT();
    };

    issue(0);
#pragma unroll 1
    for (int ic = 0; ic < NC; ic++) {
        if (ic + 1 < NC) { issue(ic + 1); CP_WAIT1(); }
        else             { CP_WAIT0(); }
        __syncthreads();
        const u32 st = sbase + (u32)((ic & 1) * STG);
#pragma unroll
        for (int s = 0; s < 4; s++) {
            const u32 bcol = (u32)(s * 32) + bcolbase;
            u32 a_h[2][4];
#pragma unroll
            for (int im = 0; im < 2; im++)
                ldsm4(a_h[im], st + AH + sw128(rowA[im] + bcol));
#pragma unroll
            for (int p = 0; p < 4; p++) {
                u32 b_h[4];
                ldsm4(b_h, st + BH + sw128(rowB[p] + bcol));
#pragma unroll
                for (int im = 0; im < 2; im++) {
                    mma16816(acc[im][2*p],   a_h[im], b_h[0], b_h[2]);
                    mma16816(acc[im][2*p+1], a_h[im], b_h[1], b_h[3]);
                }
            }
        }
        __syncthreads();
    }

    const int crow = lane >> 2;          // 0..7
    const int ccol = (lane & 3) * 2;     // 0,2,4,6
#pragma unroll
    for (int im = 0; im < 2; im++) {
#pragma unroll
        for (int j = 0; j < 8; j++) {
            const int p = j >> 1, q = j & 1;
            const int col = n0 + warp_n * 64 + p * 16 + q * 8 + ccol;
            const float2 bb = *(const float2*)(bias + col);
            const int r0g = row0 + warp_m * 32 + im * 16 + crow;
            float* a = acc[im][j];
            if (IS_G1) {
#pragma unroll
                for (int h = 0; h < 2; h++) {
                    int rg = r0g + h * 8;
                    if (rg < cnt) {
                        float v0 = fmaxf(a[2*h]   + bb.x, 0.f);
                        float v1 = fmaxf(a[2*h+1] + bb.y, 0.f);
                        __half2 ph = __halves2half2(__float2half(v0), __float2half(v1));
                        size_t o = (size_t)(base + rg) * HID + col;
                        *(u32*)(g_hid + o) = *reinterpret_cast<u32*>(&ph);
                    }
                }
            } else {
#pragma unroll
                for (int h = 0; h < 2; h++) {
                    int rg = r0g + h * 8;
                    if (rg < cnt) {
                        float g = g_gate[base + rg];
                        int tok = g_tok[base + rg];
                        float* op = outp + (size_t)tok * DIM + col;
                        atomicAdd(op,     g * (a[2*h]   + bb.x));
                        atomicAdd(op + 1, g * (a[2*h+1] + bb.y));
                    }
                }
            }
        }
    }
}

// ---------------------------------------------------------------------------
extern "C" void kernel_launch(void* const* d_in, const int* in_sizes, int n_in,
                              void* d_out, int out_size) {
    const float* x  = (const float*)d_in[0];
    const float* Wg = (const float*)d_in[1];
    const float* bg = (const float*)d_in[2];
    const float* W1 = (const float*)d_in[3];
    const float* b1 = (const float*)d_in[4];
    const float* W2 = (const float*)d_in[5];
    const float* b2 = (const float*)d_in[6];
    float* out = (float*)d_out;

    const int SMEM_SZ = 2 * 32768;   // 64 KB
    cudaFuncSetAttribute(k_gemm_mma<DIM, true>,
                         cudaFuncAttributeMaxDynamicSharedMemorySize, SMEM_SZ);
    cudaFuncSetAttribute(k_gemm_mma<HID, false>,
                         cudaFuncAttributeMaxDynamicSharedMemorySize, SMEM_SZ);

    // zero count/fill array (memset node) and d_out (RED targets)
    void* cnt_addr = nullptr;
    cudaGetSymbolAddress(&cnt_addr, g_cnt2);
    cudaMemsetAsync(cnt_addr, 0, 2 * NEXP * sizeof(int));
    cudaMemsetAsync(d_out, 0, (size_t)out_size * sizeof(float));

    k_gate<<<TOK / 8, 256>>>(x, Wg, bg);
    k_assign<<<TOK / 256, 256>>>();
    k_conv_x<<<(TOK * DIM / 4) / 256, 256>>>(x);
    k_trans_w1<<<dim3(HID / 32, DIM / 64, NEXP), dim3(32, 8)>>>(W1);
    k_trans_w2<<<dim3(DIM / 32, HID / 64, NEXP), dim3(32, 8)>>>(W2);
    k_gemm_mma<DIM, true ><<<dim3(HID / 128, TOK / 128, NEXP), 256, SMEM_SZ>>>(b1, out);
    k_gemm_mma<HID, false><<<dim3(DIM / 128, TOK / 128, NEXP), 256, SMEM_SZ>>>(b2, out);
}